// round 8
// baseline (speedup 1.0000x reference)
#include <cuda_runtime.h>
#include <cuda_bf16.h>
#include <cstdint>

// inputs:  [B=32, 56, 56, C=256] fp32 ; routing: [32, 4] fp32
// out[b,h,w,j] = inputs[b,h,w, argmax(routing[b])*64 + j]  -> [32,56,56,64]
//
// R8: cold==warm timing proved the binder is per-SM memory-instruction cost
// (LSU dispatch + L1tex wavefronts), not bytes. Use Blackwell 256-bit
// ld/st (v8.f32) to halve the instruction count at identical traffic.
// Config = R3's best (1568 blocks x 256 thr, 64B/thread), now 2x v8/thread.

namespace {
constexpr int B       = 32;
constexpr int HW      = 56 * 56;      // 3136 pixels per batch
constexpr int ROUTES  = 4;
constexpr int V8      = 8;            // v8 chunks per output pixel (64 floats)
constexpr int THREADS = 256;
constexpr int PER_TH  = 2;            // v8 per thread (64B)
constexpr int PER_BLK = THREADS * PER_TH;                  // 512 v8 = 64 pixels
constexpr long long TOTAL_V8 = (long long)B * HW * V8;     // 802,816
constexpr int BLOCKS  = (int)(TOTAL_V8 / PER_BLK);         // 1568 (exact)
constexpr int BLOCKS_PER_BATCH = BLOCKS / B;               // 49   (exact)
}

__device__ __forceinline__ void ldg_v8(const float* __restrict__ p, float r[8])
{
    asm volatile("ld.global.nc.v8.f32 {%0,%1,%2,%3,%4,%5,%6,%7}, [%8];"
                 : "=f"(r[0]), "=f"(r[1]), "=f"(r[2]), "=f"(r[3]),
                   "=f"(r[4]), "=f"(r[5]), "=f"(r[6]), "=f"(r[7])
                 : "l"(p));
}

__device__ __forceinline__ void stg_v8(float* __restrict__ p, const float r[8])
{
    asm volatile("st.global.v8.f32 [%0], {%1,%2,%3,%4,%5,%6,%7,%8};"
                 :: "l"(p),
                    "f"(r[0]), "f"(r[1]), "f"(r[2]), "f"(r[3]),
                    "f"(r[4]), "f"(r[5]), "f"(r[6]), "f"(r[7])
                 : "memory");
}

__global__ __launch_bounds__(THREADS)
void routing_gather_kernel(const float* __restrict__ in,
                           const float* __restrict__ routing,
                           float* __restrict__ out)
{
    // Block covers 512 consecutive output v8 chunks, all in one batch.
    const int b = blockIdx.x / BLOCKS_PER_BATCH;   // const-divisor -> mulhi

    // argmax over 4 logits; uniform address across block -> L1 broadcast.
    const float* r = routing + b * ROUTES;
    float best = r[0];
    int route = 0;
#pragma unroll
    for (int k = 1; k < ROUTES; ++k) {
        float v = r[k];
        if (v > best) { best = v; route = k; }   // strict > = first-max tie
    }
    const int rbase8 = route * V8;               // v8 offset of selected block

    // Warp owns 64 consecutive v8 chunks (2KB), lane-stride 32: coalesced.
    const int base = blockIdx.x * PER_BLK
                   + (threadIdx.x >> 5) * (32 * PER_TH)
                   + (threadIdx.x & 31);

    float v[PER_TH][8];
#pragma unroll
    for (int k = 0; k < PER_TH; ++k) {
        int idx = base + k * 32;                 // global output v8 index
        int t   = idx >> 3;                      // pixel index (b*HW + pix)
        int j   = idx & (V8 - 1);                // v8 within pixel
        // input v8 index: t*32 + route*8 + j  (all 32B-aligned)
        ldg_v8(in + ((long long)t * 32 + rbase8 + j) * 8, v[k]);
    }
#pragma unroll
    for (int k = 0; k < PER_TH; ++k) {
        stg_v8(out + (long long)(base + k * 32) * 8, v[k]);
    }
}

extern "C" void kernel_launch(void* const* d_in, const int* in_sizes, int n_in,
                              void* d_out, int out_size)
{
    const float* in      = (const float*)d_in[0];
    const float* routing = (const float*)d_in[1];
    float*       out     = (float*)d_out;

    routing_gather_kernel<<<BLOCKS, THREADS>>>(in, routing, out);
}

// round 9
// speedup vs baseline: 1.1940x; 1.1940x over previous
#include <cuda_runtime.h>
#include <cuda.h>
#include <cuda_bf16.h>
#include <cstdint>

// inputs:  [B=32, 56, 56, C=256] fp32 ; routing: [32, 4] fp32
// out[b,h,w,j] = inputs[b,h,w, argmax(routing[b])*64 + j]  -> [32,56,56,64]
//
// R9: all-TMA, pipelined. R2-R8 showed the per-thread LDG/STG path has a
// ~10us sector-throughput floor invariant to MLP/occupancy/vector width.
// TMA moves the bytes through LTS without the per-SMSP LSU pipe.
// 784 CTAs x 2 tiles each: BOTH tile loads issued up-front (whole grid is
// one resident wave -> ~all read traffic in flight immediately), stores
// drain via cp.async.bulk as loads complete.

namespace {
constexpr int B       = 32;
constexpr int HW      = 56 * 56;              // 3136 (= 49 * 64, exact)
constexpr int ROUTES  = 4;
constexpr int ROWS    = 64;                   // pixels per tile
constexpr int TILES   = B * HW / ROWS;        // 1568
constexpr int TILES_PER_B = HW / ROWS;        // 49
constexpr int TPC     = 2;                    // tiles per CTA
constexpr int BLOCKS  = TILES / TPC;          // 784
constexpr int TILE_FLOATS = ROWS * 64;        // 4096
constexpr int TILE_BYTES  = TILE_FLOATS * 4;  // 16384
}

__global__ __launch_bounds__(32)
void routing_tma_kernel(const __grid_constant__ CUtensorMap in_map,
                        const float* __restrict__ routing,
                        float* __restrict__ out)
{
    __shared__ alignas(1024) float tile[TPC][TILE_FLOATS];  // 32 KB
    __shared__ alignas(8) uint64_t mbar[TPC];

    if (threadIdx.x != 0) return;   // single-thread control; TMA moves data

    const int t0 = blockIdx.x * TPC;

    // Init one mbarrier per tile.
#pragma unroll
    for (int s = 0; s < TPC; ++s) {
        uint32_t mb = (uint32_t)__cvta_generic_to_shared(&mbar[s]);
        asm volatile("mbarrier.init.shared.b64 [%0], %1;"
                     :: "r"(mb), "r"(1) : "memory");
    }
    asm volatile("fence.proxy.async.shared::cta;" ::: "memory");

    // Compute routes for both tiles (batch the routing loads), then issue
    // both TMA loads back-to-back: deep in-flight read traffic.
    int coordx[TPC];
#pragma unroll
    for (int s = 0; s < TPC; ++s) {
        const int t = t0 + s;
        const int b = t / TILES_PER_B;               // const-div -> mulhi
        const float* r = routing + b * ROUTES;
        float best = r[0];
        int route = 0;
#pragma unroll
        for (int k = 1; k < ROUTES; ++k) {
            float v = r[k];
            if (v > best) { best = v; route = k; }   // strict > tie rule
        }
        coordx[s] = route * 64;                      // float offset in row
    }

#pragma unroll
    for (int s = 0; s < TPC; ++s) {
        const int t = t0 + s;
        uint32_t mb = (uint32_t)__cvta_generic_to_shared(&mbar[s]);
        uint32_t st = (uint32_t)__cvta_generic_to_shared(&tile[s][0]);
        asm volatile("mbarrier.arrive.expect_tx.shared.b64 _, [%0], %1;"
                     :: "r"(mb), "r"(TILE_BYTES) : "memory");
        asm volatile(
            "cp.async.bulk.tensor.2d.shared::cta.global.tile.mbarrier::complete_tx::bytes "
            "[%0], [%1, {%2, %3}], [%4];"
            :: "r"(st), "l"(&in_map), "r"(coordx[s]), "r"(t * ROWS), "r"(mb)
            : "memory");
    }

    // Drain: as each load completes, fire its bulk store (async, grouped).
#pragma unroll
    for (int s = 0; s < TPC; ++s) {
        uint32_t mb = (uint32_t)__cvta_generic_to_shared(&mbar[s]);
        uint32_t done;
        asm volatile(
            "{\n\t.reg .pred p;\n\t"
            "mbarrier.try_wait.parity.acquire.cta.shared::cta.b64 p, [%1], %2;\n\t"
            "selp.b32 %0, 1, 0, p;\n\t}"
            : "=r"(done) : "r"(mb), "r"(0u) : "memory");
        while (!done) {
            asm volatile(
                "{\n\t.reg .pred p;\n\t"
                "mbarrier.try_wait.parity.acquire.cta.shared::cta.b64 p, [%1], %2, 0x989680;\n\t"
                "selp.b32 %0, 1, 0, p;\n\t}"
                : "=r"(done) : "r"(mb), "r"(0u) : "memory");
        }
        uint32_t st = (uint32_t)__cvta_generic_to_shared(&tile[s][0]);
        float* dst = out + (long long)(t0 + s) * TILE_FLOATS;
        asm volatile("cp.async.bulk.global.shared::cta.bulk_group [%0], [%1], %2;"
                     :: "l"(dst), "r"(st), "r"(TILE_BYTES) : "memory");
        asm volatile("cp.async.bulk.commit_group;" ::: "memory");
    }
    // SMEM must outlive the async stores: wait before CTA exit.
    asm volatile("cp.async.bulk.wait_group 0;" ::: "memory");
}

extern "C" void kernel_launch(void* const* d_in, const int* in_sizes, int n_in,
                              void* d_out, int out_size)
{
    const float* in      = (const float*)d_in[0];
    const float* routing = (const float*)d_in[1];
    float*       out     = (float*)d_out;

    // 2D tensor map: rows = B*HW (pitch 1024B), inner 256 floats.
    typedef CUresult (*EncodeFn)(
        CUtensorMap*, CUtensorMapDataType, cuuint32_t, void*,
        const cuuint64_t*, const cuuint64_t*, const cuuint32_t*, const cuuint32_t*,
        CUtensorMapInterleave, CUtensorMapSwizzle, CUtensorMapL2promotion,
        CUtensorMapFloatOOBfill);
    void* fn_ptr = nullptr;
    cudaDriverEntryPointQueryResult qres;
    cudaGetDriverEntryPoint("cuTensorMapEncodeTiled", &fn_ptr,
                            cudaEnableDefault, &qres);
    EncodeFn encode = (EncodeFn)fn_ptr;

    CUtensorMap in_map;
    cuuint64_t dims[2]    = {256, (cuuint64_t)B * HW};
    cuuint64_t strides[1] = {256 * sizeof(float)};
    cuuint32_t box[2]     = {64, ROWS};                 // 256B x 64 rows
    cuuint32_t estr[2]    = {1, 1};
    encode(&in_map, CU_TENSOR_MAP_DATA_TYPE_FLOAT32, 2, (void*)in,
           dims, strides, box, estr,
           CU_TENSOR_MAP_INTERLEAVE_NONE, CU_TENSOR_MAP_SWIZZLE_NONE,
           CU_TENSOR_MAP_L2_PROMOTION_L2_128B, CU_TENSOR_MAP_FLOAT_OOB_FILL_NONE);

    routing_tma_kernel<<<BLOCKS, 32>>>(in_map, routing, out);
}